// round 1
// baseline (speedup 1.0000x reference)
#include <cuda_runtime.h>
#include <math.h>

// Problem constants (B=64, T=500, C=40)
#define CC   40
#define CP1  41          // gmem row stride of y_pred last dim
#define RS   44          // smem row stride (16B-aligned rows, conflict-free LDS.128)
#define NB   8           // Cholesky block size
#define WPB  4           // warps (matrices) per block
#define MATG (CC*CP1)    // 1640 floats per matrix in gmem

__device__ double g_acc;

__global__ void zero_kernel() { g_acc = 0.0; }

__global__ void __launch_bounds__(WPB*32)
nll_kernel(const float* __restrict__ yt, const float* __restrict__ yp, int nmat)
{
    // per warp: matrix 40*44 = 1760 floats + rhs 40 floats
    __shared__ float  smem[WPB][CC*RS + CC];
    __shared__ double wacc[WPB];

    const int lane = threadIdx.x & 31;
    const int warp = threadIdx.x >> 5;
    const int m    = blockIdx.x * WPB + warp;

    float acc = 0.0f;

    float* s = smem[warp];
    float* r = s + CC*RS;

    if (m < nmat) {
        // ---- load sigma+mu (linear, coalesced float4) into stride-44 smem ----
        const float4* gp = (const float4*)(yp + (size_t)m * MATG);
        for (int v = lane; v < MATG/4; v += 32) {
            float4 q = gp[v];
            int e = v << 2;
            int i = e / CP1;            // magic-multiply division
            int j = e - i * CP1;
            float* p = s + i*RS + j;
            // elements may wrap to next row once; wrapped index = idx + (RS-CP1) = idx+3
            p[0] = q.x;
            p[(j+1 >= CP1) ? 4 : 1] = q.y;
            p[(j+2 >= CP1) ? 5 : 2] = q.z;
            p[(j+3 >= CP1) ? 6 : 3] = q.w;
        }
        __syncwarp();

        // ---- rhs: diff = y_true - mu (mu is column 40) ----
        const float* ytm = yt + (size_t)m * CC;
        for (int i = lane; i < CC; i += 32)
            r[i] = ytm[i] - s[i*RS + CC];
        __syncwarp();

        float quadhalf = 0.f, logdet = 0.f;

        // ---- blocked Cholesky (right-looking, NB=8) with fused forward solve ----
        #pragma unroll
        for (int kb = 0; kb < CC; kb += NB) {
            // --- panel factorization: columns kb .. kb+7, all rows, cols < kb+8 ---
            #pragma unroll
            for (int t = 0; t < NB; t++) {
                const int k = kb + t;
                float d   = sqrtf(s[k*RS + k]);    // broadcast read; same on all lanes
                float inv = 1.0f / d;
                logdet   += logf(d);
                float zk  = r[k] * inv;            // forward-substitution step k
                quadhalf += 0.5f * zk * zk;

                // scale column k below diagonal
                for (int i = k + 1 + lane; i < CC; i += 32)
                    s[i*RS + k] *= inv;
                __syncwarp();

                // rank-1 update restricted to panel columns + solve update
                for (int i = k + 1 + lane; i < CC; i += 32) {
                    float lik = s[i*RS + k];
                    #pragma unroll
                    for (int j = k + 1; j < kb + NB; j++)   // trip = NB-1-t (compile-time)
                        s[i*RS + j] -= lik * s[j*RS + k];
                    r[i] -= lik * zk;
                }
                __syncwarp();
            }

            // --- trailing rank-8 update: rows/cols >= kb+8 (lower triangle) ---
            if (kb + NB < CC) {
                const int i = kb + NB + lane;           // one row per lane
                if (i < CC) {
                    const float4* ap = (const float4*)(s + i*RS + kb);
                    float4 A0 = ap[0], A1 = ap[1];      // this row's 8 panel multipliers
                    float a[NB] = {A0.x,A0.y,A0.z,A0.w,A1.x,A1.y,A1.z,A1.w};
                    for (int jb = kb + NB; jb <= i; jb += 4) {
                        float4 c = *(const float4*)(s + i*RS + jb);
                        float cv[4] = {c.x, c.y, c.z, c.w};
                        #pragma unroll
                        for (int q = 0; q < 4; q++) {
                            // broadcast loads: all active lanes read row (jb+q)'s panel
                            const float4* bp = (const float4*)(s + (jb + q)*RS + kb);
                            float4 b0 = bp[0], b1 = bp[1];
                            cv[q] -= a[0]*b0.x + a[1]*b0.y + a[2]*b0.z + a[3]*b0.w
                                   + a[4]*b1.x + a[5]*b1.y + a[6]*b1.z + a[7]*b1.w;
                        }
                        // j>i spill cells stay within the padded row and are never read
                        *(float4*)(s + i*RS + jb) = make_float4(cv[0],cv[1],cv[2],cv[3]);
                    }
                }
                __syncwarp();
            }
        }
        acc = quadhalf + logdet;   // identical on every lane
    }

    // ---- block reduction, one double atomic per block ----
    if (lane == 0) wacc[warp] = (double)acc;
    __syncthreads();
    if (threadIdx.x == 0) {
        double tsum = 0.0;
        #pragma unroll
        for (int w = 0; w < WPB; w++) tsum += wacc[w];
        atomicAdd(&g_acc, tsum);
    }
}

__global__ void fin_kernel(float* out)
{
    // result = sum(0.5*quad + logdet_half)/B + T*(C/2)*log(2*pi)
    const double LOG2PI = 1.8378770664093453;
    out[0] = (float)(g_acc / 64.0 + 500.0 * 20.0 * LOG2PI);
}

extern "C" void kernel_launch(void* const* d_in, const int* in_sizes, int n_in,
                              void* d_out, int out_size)
{
    // identify inputs by size (y_true is the small one)
    int i_yt = 0, i_yp = 1;
    if (n_in >= 2 && in_sizes[0] > in_sizes[1]) { i_yt = 1; i_yp = 0; }
    const float* yt = (const float*)d_in[i_yt];
    const float* yp = (const float*)d_in[i_yp];
    int nmat = in_sizes[i_yt] / CC;           // 32000

    zero_kernel<<<1, 1>>>();
    int blocks = (nmat + WPB - 1) / WPB;
    nll_kernel<<<blocks, WPB*32>>>(yt, yp, nmat);
    fin_kernel<<<1, 1>>>((float*)d_out);
}

// round 3
// speedup vs baseline: 1.6499x; 1.6499x over previous
#include <cuda_runtime.h>
#include <math.h>

// Problem constants (B=64, T=500, C=40)
#define CC   40
#define CP1  41          // gmem row stride of y_pred last dim
#define RS   44          // smem row stride (16B-aligned rows, conflict-free LDS.128)
#define NB   8           // Cholesky block size
#define WPB  4           // warps (matrices) per block
#define MATG (CC*CP1)    // 1640 floats per matrix in gmem
#define FULLM 0xFFFFFFFFu

__device__ double g_part[8192];   // per-block partial sums (overwritten every launch)

__global__ void __launch_bounds__(WPB*32)
nll_kernel(const float* __restrict__ yt, const float* __restrict__ yp, int nmat)
{
    // per warp: matrix 40*44 = 1760 floats + rhs 40 floats
    __shared__ float  smem[WPB][CC*RS + CC];
    __shared__ double wacc[WPB];

    const int lane = threadIdx.x & 31;
    const int warp = threadIdx.x >> 5;
    const int m    = blockIdx.x * WPB + warp;

    float acc = 0.0f;

    float* s = smem[warp];
    float* r = s + CC*RS;

    if (m < nmat) {
        // ---- load sigma+mu (linear, coalesced float4) into stride-44 smem ----
        const float4* gp = (const float4*)(yp + (size_t)m * MATG);
        for (int v = lane; v < MATG/4; v += 32) {
            float4 q = gp[v];
            int e = v << 2;
            int i = e / CP1;            // magic-multiply division
            int j = e - i * CP1;
            float* p = s + i*RS + j;
            // elements may wrap to next row once; wrapped offset = +RS-CP1 = +3
            p[0] = q.x;
            p[(j+1 >= CP1) ? 4 : 1] = q.y;
            p[(j+2 >= CP1) ? 5 : 2] = q.z;
            p[(j+3 >= CP1) ? 6 : 3] = q.w;
        }
        __syncwarp();

        // ---- rhs: diff = y_true - mu (mu is column 40) ----
        const float* ytm = yt + (size_t)m * CC;
        for (int i = lane; i < CC; i += 32)
            r[i] = ytm[i] - s[i*RS + CC];
        __syncwarp();

        float quad2 = 0.f, logdet = 0.f;   // quad2 = sum z^2

        // ---- blocked Cholesky, register-resident panel, fused forward solve ----
        #pragma unroll
        for (int kb = 0; kb < CC; kb += NB) {
            const bool own  = lane < (CC - kb);               // lane owns row kb+lane
            const bool own2 = (kb == 0) && (lane < CC - 32);  // extra rows 32..39

            float a[NB] = {0,0,0,0,0,0,0,0};
            float b[NB] = {0,0,0,0,0,0,0,0};
            float rr = 0.f, rr2 = 0.f;

            if (own) {
                const float4* ap = (const float4*)(s + (kb + lane)*RS + kb);
                float4 A0 = ap[0], A1 = ap[1];
                a[0]=A0.x; a[1]=A0.y; a[2]=A0.z; a[3]=A0.w;
                a[4]=A1.x; a[5]=A1.y; a[6]=A1.z; a[7]=A1.w;
                rr = r[kb + lane];
            }
            if (own2) {
                const float4* bp = (const float4*)(s + (32 + lane)*RS);
                float4 B0 = bp[0], B1 = bp[1];
                b[0]=B0.x; b[1]=B0.y; b[2]=B0.z; b[3]=B0.w;
                b[4]=B1.x; b[5]=B1.y; b[6]=B1.z; b[7]=B1.w;
                rr2 = r[32 + lane];
            }

            // 8 factorization steps entirely in registers + shuffles.
            // All shuffles executed by all 32 lanes (fully converged).
            #pragma unroll
            for (int t = 0; t < NB; t++) {
                float diag = __shfl_sync(FULLM, a[t], t);
                float d    = sqrtf(diag);
                float inv  = __fdividef(1.0f, d);
                logdet    += __logf(d);
                float zk   = __shfl_sync(FULLM, rr, t) * inv;
                quad2      = fmaf(zk, zk, quad2);

                float lit = a[t] * inv;           // scaled col-t value (valid on lanes > t)
                float cv[NB];
                #pragma unroll
                for (int j = t + 1; j < NB; j++)
                    cv[j] = __shfl_sync(FULLM, lit, j);   // L[kb+j][k]

                if (own) {
                    if (lane > t) {
                        a[t] = lit;
                        #pragma unroll
                        for (int j = t + 1; j < NB; j++)
                            a[j] = fmaf(-lit, cv[j], a[j]);
                        rr = fmaf(-lit, zk, rr);
                    } else if (lane == t) {
                        a[t] = d;                 // diagonal of L
                    }
                }
                if (own2) {                       // rows 32..39, always below k
                    float l2 = b[t] * inv;
                    b[t] = l2;
                    #pragma unroll
                    for (int j = t + 1; j < NB; j++)
                        b[j] = fmaf(-l2, cv[j], b[j]);
                    rr2 = fmaf(-l2, zk, rr2);
                }
            }

            // write finalized panel back for the trailing update
            if (own) {
                float4* ap = (float4*)(s + (kb + lane)*RS + kb);
                ap[0] = make_float4(a[0],a[1],a[2],a[3]);
                ap[1] = make_float4(a[4],a[5],a[6],a[7]);
                r[kb + lane] = rr;
            }
            if (own2) {
                float4* bp = (float4*)(s + (32 + lane)*RS);
                bp[0] = make_float4(b[0],b[1],b[2],b[3]);
                bp[1] = make_float4(b[4],b[5],b[6],b[7]);
                r[32 + lane] = rr2;
            }
            __syncwarp();

            // --- trailing rank-8 update: rows/cols >= kb+8 (lower triangle) ---
            if (kb + NB < CC) {
                const int i = kb + NB + lane;           // one row per lane
                if (i < CC) {
                    const float4* ap = (const float4*)(s + i*RS + kb);
                    float4 A0 = ap[0], A1 = ap[1];      // this row's 8 panel multipliers
                    float av[NB] = {A0.x,A0.y,A0.z,A0.w,A1.x,A1.y,A1.z,A1.w};
                    for (int jb = kb + NB; jb <= i; jb += 4) {
                        float4 c = *(const float4*)(s + i*RS + jb);
                        float cvv[4] = {c.x, c.y, c.z, c.w};
                        #pragma unroll
                        for (int q = 0; q < 4; q++) {
                            // broadcast loads: all active lanes read row (jb+q)'s panel
                            const float4* bp = (const float4*)(s + (jb + q)*RS + kb);
                            float4 b0 = bp[0], b1 = bp[1];
                            cvv[q] -= av[0]*b0.x + av[1]*b0.y + av[2]*b0.z + av[3]*b0.w
                                    + av[4]*b1.x + av[5]*b1.y + av[6]*b1.z + av[7]*b1.w;
                        }
                        // j>i spill cells stay within the padded row and are never read
                        *(float4*)(s + i*RS + jb) = make_float4(cvv[0],cvv[1],cvv[2],cvv[3]);
                    }
                }
                __syncwarp();
            }
        }
        acc = 0.5f*quad2 + logdet;   // identical on every lane
    }

    // ---- block reduction, one partial per block (no atomics, no zeroing) ----
    if (lane == 0) wacc[warp] = (double)acc;
    __syncthreads();
    if (threadIdx.x == 0 && blockIdx.x < 8192) {
        double tsum = 0.0;
        #pragma unroll
        for (int w = 0; w < WPB; w++) tsum += wacc[w];
        g_part[blockIdx.x] = tsum;
    }
}

__global__ void __launch_bounds__(256)
fin_kernel(float* out, int nblocks)
{
    __shared__ double red[256];
    double ssum = 0.0;
    for (int i = threadIdx.x; i < nblocks; i += 256) ssum += g_part[i];
    red[threadIdx.x] = ssum;
    __syncthreads();
    for (int h = 128; h > 0; h >>= 1) {
        if (threadIdx.x < h) red[threadIdx.x] += red[threadIdx.x + h];
        __syncthreads();
    }
    if (threadIdx.x == 0) {
        // result = sum(0.5*quad + logdet_half)/B + T*(C/2)*log(2*pi)
        const double LOG2PI = 1.8378770664093453;
        out[0] = (float)(red[0] / 64.0 + 500.0 * 20.0 * LOG2PI);
    }
}

extern "C" void kernel_launch(void* const* d_in, const int* in_sizes, int n_in,
                              void* d_out, int out_size)
{
    // identify inputs by size (y_true is the small one)
    int i_yt = 0, i_yp = 1;
    if (n_in >= 2 && in_sizes[0] > in_sizes[1]) { i_yt = 1; i_yp = 0; }
    const float* yt = (const float*)d_in[i_yt];
    const float* yp = (const float*)d_in[i_yp];
    int nmat = in_sizes[i_yt] / CC;           // 32000

    int blocks = (nmat + WPB - 1) / WPB;      // 8000 (fits g_part[8192])
    if (blocks > 8192) blocks = 8192;
    nll_kernel<<<blocks, WPB*32>>>(yt, yp, nmat);
    fin_kernel<<<1, 256>>>((float*)d_out, blocks);
}

// round 6
// speedup vs baseline: 1.8964x; 1.1494x over previous
#include <cuda_runtime.h>
#include <math.h>

// Problem constants (B=64, T=500, C=40)
#define CC   40
#define CP1  41          // gmem row stride of y_pred last dim
#define RS   44          // smem row stride (16B-aligned rows, conflict-free LDS.128)
#define NB   8           // Cholesky block size
#define WPB  4           // warps (matrices) per block
#define MATG (CC*CP1)    // 1640 floats per matrix in gmem
#define FULLM 0xFFFFFFFFu

__device__ double g_part[8192];   // per-block partial sums (overwritten every launch)

__global__ void __launch_bounds__(WPB*32)
nll_kernel(const float* __restrict__ yt, const float* __restrict__ yp, int nmat)
{
    // per warp: matrix 40*44 = 1760 floats + rhs 40 floats
    __shared__ float  smem[WPB][CC*RS + CC];
    __shared__ double wacc[WPB];

    const int lane = threadIdx.x & 31;
    const int warp = threadIdx.x >> 5;
    const int m    = blockIdx.x * WPB + warp;

    float acc = 0.0f;

    float* s = smem[warp];
    float* r = s + CC*RS;

    if (m < nmat) {
        // ---- load sigma+mu (linear, coalesced float4) into stride-44 smem ----
        const float4* gp = (const float4*)(yp + (size_t)m * MATG);
        for (int v = lane; v < MATG/4; v += 32) {
            float4 q = gp[v];
            int e = v << 2;
            int i = e / CP1;            // magic-multiply division
            int j = e - i * CP1;
            float* p = s + i*RS + j;
            // elements may wrap to next row once; wrapped offset = +RS-CP1 = +3
            p[0] = q.x;
            p[(j+1 >= CP1) ? 4 : 1] = q.y;
            p[(j+2 >= CP1) ? 5 : 2] = q.z;
            p[(j+3 >= CP1) ? 6 : 3] = q.w;
        }
        __syncwarp();

        // ---- rhs: diff = y_true - mu (mu is column 40) ----
        const float* ytm = yt + (size_t)m * CC;
        for (int i = lane; i < CC; i += 32)
            r[i] = ytm[i] - s[i*RS + CC];
        __syncwarp();

        float quad2 = 0.f;          // sum z^2
        float logsum = 0.f;         // sum log(diag)  (= 2 * logdet_half)

        // ---- blocked Cholesky, register-resident panel, fused forward solve ----
        #pragma unroll
        for (int kb = 0; kb < CC; kb += NB) {
            const bool own  = lane < (CC - kb);               // lane owns row kb+lane
            const bool own2 = (kb == 0) && (lane < CC - 32);  // extra rows 32..39

            float a[NB] = {0,0,0,0,0,0,0,0};
            float b[NB] = {0,0,0,0,0,0,0,0};
            float rr = 0.f, rr2 = 0.f;

            if (own) {
                const float4* ap = (const float4*)(s + (kb + lane)*RS + kb);
                float4 A0 = ap[0], A1 = ap[1];
                a[0]=A0.x; a[1]=A0.y; a[2]=A0.z; a[3]=A0.w;
                a[4]=A1.x; a[5]=A1.y; a[6]=A1.z; a[7]=A1.w;
                rr = r[kb + lane];
            }
            if (own2) {
                const float4* bp = (const float4*)(s + (32 + lane)*RS);
                float4 B0 = bp[0], B1 = bp[1];
                b[0]=B0.x; b[1]=B0.y; b[2]=B0.z; b[3]=B0.w;
                b[4]=B1.x; b[5]=B1.y; b[6]=B1.z; b[7]=B1.w;
                rr2 = r[32 + lane];
            }

            float dp = 1.0f;   // product of 8 panel diagonals

            // 8 factorization steps, branchless: cells above the diagonal and
            // already-solved rhs entries get harmlessly corrupted (never read).
            #pragma unroll
            for (int t = 0; t < NB; t++) {
                float diag = __shfl_sync(FULLM, a[t], t);   // lane t holds true diag
                float inv  = rsqrtf(diag);                  // single MUFU
                dp        *= diag;
                float zk   = __shfl_sync(FULLM, rr, t) * inv;
                quad2      = fmaf(zk, zk, quad2);

                float lit = a[t] * inv;
                float cv[NB];
                #pragma unroll
                for (int j = t + 1; j < NB; j++)
                    cv[j] = __shfl_sync(FULLM, lit, j);     // L[kb+j][k]

                // uniform update (lane==t naturally stores ~sqrt(diag))
                a[t] = lit;
                #pragma unroll
                for (int j = t + 1; j < NB; j++)
                    a[j] = fmaf(-lit, cv[j], a[j]);
                rr = fmaf(-lit, zk, rr);

                if (own2) {                       // rows 32..39 (kb==0 only)
                    float l2 = b[t] * inv;
                    b[t] = l2;
                    #pragma unroll
                    for (int j = t + 1; j < NB; j++)
                        b[j] = fmaf(-l2, cv[j], b[j]);
                    rr2 = fmaf(-l2, zk, rr2);
                }
            }
            logsum += __logf(dp);   // one log per panel (dp bounded, fp32-safe)

            // write finalized panel back for the trailing update
            if (own) {
                float4* ap = (float4*)(s + (kb + lane)*RS + kb);
                ap[0] = make_float4(a[0],a[1],a[2],a[3]);
                ap[1] = make_float4(a[4],a[5],a[6],a[7]);
                r[kb + lane] = rr;
            }
            if (own2) {
                float4* bp = (float4*)(s + (32 + lane)*RS);
                bp[0] = make_float4(b[0],b[1],b[2],b[3]);
                bp[1] = make_float4(b[4],b[5],b[6],b[7]);
                r[32 + lane] = rr2;
            }
            __syncwarp();

            // --- trailing rank-8 update, rectangular & fully unrolled ---
            // Uniform jb bound: cells with j>i are garbage but provably never
            // consumed (stay inside the padded row). Same warp-cycles as the
            // triangular version, zero divergence, immediate-offset LDS/STS.
            if (kb + NB < CC) {
                const int i = kb + NB + lane;           // one row per lane
                if (i < CC) {
                    const float4* ap = (const float4*)(s + i*RS + kb);
                    float4 A0 = ap[0], A1 = ap[1];      // this row's 8 panel multipliers
                    float av[NB] = {A0.x,A0.y,A0.z,A0.w,A1.x,A1.y,A1.z,A1.w};
                    #pragma unroll
                    for (int jb = kb + NB; jb <= 36; jb += 4) {
                        float4 c = *(const float4*)(s + i*RS + jb);
                        float cvv[4] = {c.x, c.y, c.z, c.w};
                        #pragma unroll
                        for (int q = 0; q < 4; q++) {
                            // broadcast loads: all lanes read row (jb+q)'s panel
                            const float4* bp = (const float4*)(s + (jb + q)*RS + kb);
                            float4 b0 = bp[0], b1 = bp[1];
                            cvv[q] -= av[0]*b0.x + av[1]*b0.y + av[2]*b0.z + av[3]*b0.w
                                    + av[4]*b1.x + av[5]*b1.y + av[6]*b1.z + av[7]*b1.w;
                        }
                        *(float4*)(s + i*RS + jb) = make_float4(cvv[0],cvv[1],cvv[2],cvv[3]);
                    }
                }
                __syncwarp();
            }
        }
        acc = 0.5f*quad2 + 0.5f*logsum;   // identical on every lane
    }

    // ---- block reduction, one partial per block (no atomics) ----
    if (lane == 0) wacc[warp] = (double)acc;
    __syncthreads();
    if (threadIdx.x == 0 && blockIdx.x < 8192) {
        double tsum = 0.0;
        #pragma unroll
        for (int w = 0; w < WPB; w++) tsum += wacc[w];
        g_part[blockIdx.x] = tsum;
    }
}

__global__ void __launch_bounds__(256)
fin_kernel(float* out, int nblocks)
{
    __shared__ double red[256];
    double ssum = 0.0;
    for (int i = threadIdx.x; i < nblocks; i += 256) ssum += g_part[i];
    red[threadIdx.x] = ssum;
    __syncthreads();
    for (int h = 128; h > 0; h >>= 1) {
        if (threadIdx.x < h) red[threadIdx.x] += red[threadIdx.x + h];
        __syncthreads();
    }
    if (threadIdx.x == 0) {
        // result = sum(0.5*quad + logdet_half)/B + T*(C/2)*log(2*pi)
        const double LOG2PI = 1.8378770664093453;
        out[0] = (float)(red[0] / 64.0 + 500.0 * 20.0 * LOG2PI);
    }
}

extern "C" void kernel_launch(void* const* d_in, const int* in_sizes, int n_in,
                              void* d_out, int out_size)
{
    // identify inputs by size (y_true is the small one)
    int i_yt = 0, i_yp = 1;
    if (n_in >= 2 && in_sizes[0] > in_sizes[1]) { i_yt = 1; i_yp = 0; }
    const float* yt = (const float*)d_in[i_yt];
    const float* yp = (const float*)d_in[i_yp];
    int nmat = in_sizes[i_yt] / CC;           // 32000

    int blocks = (nmat + WPB - 1) / WPB;      // 8000 (fits g_part[8192])
    if (blocks > 8192) blocks = 8192;
    nll_kernel<<<blocks, WPB*32>>>(yt, yp, nmat);
    fin_kernel<<<1, 256>>>((float*)d_out, blocks);
}